// round 17
// baseline (speedup 1.0000x reference)
#include <cuda_runtime.h>
#include <cuda_bf16.h>
#include <cuda_fp16.h>
#include <cstdint>

#define NN 100000
#define EE 3200000
#define KK 128
#define KP 136      // padded smem row stride (elems): 272B = 68 words -> conflict-free frags
#define CAP 80      // fixed bucket capacity per node (deg ~ Poisson(32), max@100K ~59)
#define SPILLMAX 4096
#define H0 50048    // chunk split (391 * 128)

// ---------------- scratch (device globals; no allocations) ----------------
__device__ float g_bufA[NN * 128];
__device__ float g_bufC[NN * 128];
__device__ __half g_bufHA[NN * 128];  // fp16 premultiplied GEMM output, ping
__device__ __half g_bufHB[NN * 128];  // fp16 premultiplied GEMM output, pong
__device__ int   g_cnt[NN];           // slot cursor during fill; == degree afterwards
__device__ int   g_ecol[NN * CAP];    // fixed-stride edge buckets
__device__ int2  g_spill[SPILLMAX];   // overflow edges {dst, src} (expected empty)
__device__ int   g_spillCnt;
__device__ int   g_is64;
// split weights, [N][K] layout with stride KP
__device__ unsigned short g_Wsplit[6][128 * KP];

// ---------------- warp mma helper (baseline PTX, valid on sm_103) ----------------
__device__ __forceinline__ void mma16816(float* c, const uint32_t* a, uint32_t b0, uint32_t b1) {
    asm volatile(
        "mma.sync.aligned.m16n8k16.row.col.f32.bf16.bf16.f32 "
        "{%0,%1,%2,%3}, {%4,%5,%6,%7}, {%8,%9}, {%0,%1,%2,%3};"
        : "+f"(c[0]), "+f"(c[1]), "+f"(c[2]), "+f"(c[3])
        : "r"(a[0]), "r"(a[1]), "r"(a[2]), "r"(a[3]), "r"(b0), "r"(b1));
}

// ---------------- zero counters + edge dtype detection (merged) ----------------
__global__ void k_zerodetect(const unsigned int* __restrict__ ei_raw) {
    int i = blockIdx.x * blockDim.x + threadIdx.x;
    if (i < NN) g_cnt[i] = 0;
    if (i == 0) g_spillCnt = 0;
    if (blockIdx.x == 0) {
        __shared__ unsigned int red[8];
        unsigned int o = 0;
        for (int j = threadIdx.x; j < 2048; j += 256) o |= ei_raw[2 * j + 1];
#pragma unroll
        for (int off = 16; off; off >>= 1) o |= __shfl_xor_sync(0xffffffffu, o, off);
        if ((threadIdx.x & 31) == 0) red[threadIdx.x >> 5] = o;
        __syncthreads();
        if (threadIdx.x == 0) {
            unsigned int t = 0;
#pragma unroll
            for (int j = 0; j < 8; j++) t |= red[j];
            g_is64 = (t == 0u) ? 1 : 0;
        }
    }
}

__device__ __forceinline__ int clampN(long long v) {
    return (int)min((long long)(NN - 1), max(0ll, v));
}

// ---------------- single-pass bucket fill (2 edges/thread, vector loads) ----------------
__global__ void k_fillc(const void* __restrict__ ei) {
    int t = blockIdx.x * blockDim.x + threadIdx.x;   // pair index
    if (t >= EE / 2) return;
    int d0, d1, s0, s1;
    if (g_is64) {
        const longlong2* p64 = (const longlong2*)ei;
        longlong2 dd = p64[EE / 2 + t];
        longlong2 ss = p64[t];
        d0 = clampN(dd.x); d1 = clampN(dd.y);
        s0 = clampN(ss.x); s1 = clampN(ss.y);
    } else {
        const int2* p32 = (const int2*)ei;
        int2 dd = p32[EE / 2 + t];
        int2 ss = p32[t];
        d0 = clampN(dd.x); d1 = clampN(dd.y);
        s0 = clampN(ss.x); s1 = clampN(ss.y);
    }
    int slot0 = atomicAdd(&g_cnt[d0], 1);
    if (slot0 < CAP) g_ecol[d0 * CAP + slot0] = s0;
    else { int sp = atomicAdd(&g_spillCnt, 1); if (sp < SPILLMAX) g_spill[sp] = make_int2(d0, s0); }
    int slot1 = atomicAdd(&g_cnt[d1], 1);
    if (slot1 < CAP) g_ecol[d1 * CAP + slot1] = s1;
    else { int sp = atomicAdd(&g_spillCnt, 1); if (sp < SPILLMAX) g_spill[sp] = make_int2(d1, s1); }
}

// ---------------- weight prep: W[K][N] fp32 -> hi/lo bf16 in [N][K] (stride KP) ----------------
__global__ void k_prepW(const float* __restrict__ W, int ncol,
                        unsigned short* __restrict__ bh, unsigned short* __restrict__ bl)
{
    int e = blockIdx.x * blockDim.x + threadIdx.x;
    if (e >= ncol * KK) return;
    int k = e / ncol, n = e % ncol;
    float w = W[e];
    __nv_bfloat16 h = __float2bfloat16(w);
    __nv_bfloat16 l = __float2bfloat16(w - __bfloat162float(h));
    bh[n * KP + k] = *(unsigned short*)&h;
    bl[n * KP + k] = *(unsigned short*)&l;
}

// ---------------- input projection: h = relu(x @ W_in + b_in) ----------------
__global__ __launch_bounds__(256) void k_inproj(
    const float* __restrict__ x, const float* __restrict__ Wi,
    const float* __restrict__ bi, float* __restrict__ h)
{
    __shared__ __align__(16) float Ws[7 * 128];
    for (int t = threadIdx.x; t < 7 * 128; t += 256) Ws[t] = Wi[t];
    __syncthreads();

    int gid = blockIdx.x * 256 + threadIdx.x;
    int i = gid >> 5, c = gid & 31;
    if (i >= NN) return;

    float xr[7];
#pragma unroll
    for (int k = 0; k < 7; k++) xr[k] = x[i * 7 + k];

    const float4* Ws4 = (const float4*)Ws;
    float4 acc = ((const float4*)bi)[c];
#pragma unroll
    for (int k = 0; k < 7; k++) {
        float4 w = Ws4[k * 32 + c];
        acc.x = fmaf(xr[k], w.x, acc.x);
        acc.y = fmaf(xr[k], w.y, acc.y);
        acc.z = fmaf(xr[k], w.z, acc.z);
        acc.w = fmaf(xr[k], w.w, acc.w);
    }
    acc.x = fmaxf(acc.x, 0.f); acc.y = fmaxf(acc.y, 0.f);
    acc.z = fmaxf(acc.z, 0.f); acc.w = fmaxf(acc.w, 0.f);
    ((float4*)h)[i * 32 + c] = acc;
}

// ---------------- tensor-core GEMM via mma.sync: Hout(fp16) = dinv .* (A[rows] @ W) ----------------
template <int NCOL>
__global__ __launch_bounds__(256) void k_mma(
    const float* __restrict__ A,
    const unsigned short* __restrict__ BH, const unsigned short* __restrict__ BL,
    __half* __restrict__ Hout, int base)
{
    extern __shared__ unsigned short sm[];
    constexpr int A_HI = 0;
    constexpr int A_LO = 128 * KP;
    constexpr int B_HI = 2 * 128 * KP;
    constexpr int B_LO = 2 * 128 * KP + NCOL * KP;
    constexpr int WN = NCOL / 2;
    constexpr int NT = WN / 8;

    int tid = threadIdx.x;
    int wid = tid >> 5, lane = tid & 31;
    int g = lane >> 2, t = lane & 3;
    int wm = wid & 3, wn = wid >> 2;
    int m0 = base + blockIdx.x * 128;

    // ---- stage A: fp32 -> hi/lo bf16, padded smem ----
#pragma unroll 4
    for (int j = 0; j < 16; j++) {
        int i = tid + j * 256;
        int m = i >> 5, k4 = i & 31, k = k4 << 2;
        int row = min(m0 + m, NN - 1);
        float4 a = ((const float4*)A)[(size_t)row * 32 + k4];
        __nv_bfloat16 h0 = __float2bfloat16(a.x), h1 = __float2bfloat16(a.y);
        __nv_bfloat16 h2 = __float2bfloat16(a.z), h3 = __float2bfloat16(a.w);
        __nv_bfloat16 l0 = __float2bfloat16(a.x - __bfloat162float(h0));
        __nv_bfloat16 l1 = __float2bfloat16(a.y - __bfloat162float(h1));
        __nv_bfloat16 l2 = __float2bfloat16(a.z - __bfloat162float(h2));
        __nv_bfloat16 l3 = __float2bfloat16(a.w - __bfloat162float(h3));
        uint32_t h01 = ((uint32_t)*(unsigned short*)&h1 << 16) | *(unsigned short*)&h0;
        uint32_t h23 = ((uint32_t)*(unsigned short*)&h3 << 16) | *(unsigned short*)&h2;
        uint32_t l01 = ((uint32_t)*(unsigned short*)&l1 << 16) | *(unsigned short*)&l0;
        uint32_t l23 = ((uint32_t)*(unsigned short*)&l3 << 16) | *(unsigned short*)&l2;
        *(uint2*)&sm[A_HI + m * KP + k] = make_uint2(h01, h23);
        *(uint2*)&sm[A_LO + m * KP + k] = make_uint2(l01, l23);
    }
    // ---- stage B: raw copy ----
    {
        constexpr int CNT = NCOL * KP / 8;
        const uint4* gh = (const uint4*)BH;
        const uint4* gl = (const uint4*)BL;
        uint4* shh = (uint4*)&sm[B_HI];
        uint4* sll = (uint4*)&sm[B_LO];
        for (int i = tid; i < CNT; i += 256) { shh[i] = gh[i]; sll[i] = gl[i]; }
    }
    __syncthreads();

    float acc[2][NT][4];
#pragma unroll
    for (int mt = 0; mt < 2; mt++)
#pragma unroll
        for (int nt = 0; nt < NT; nt++)
#pragma unroll
            for (int q = 0; q < 4; q++) acc[mt][nt][q] = 0.f;

#pragma unroll
    for (int pass = 0; pass < 3; pass++) {
        const unsigned short* aS = sm + ((pass == 1) ? A_LO : A_HI);
        const unsigned short* bS = sm + ((pass == 2) ? B_LO : B_HI);
        int am = wm * 32;
#pragma unroll
        for (int k0 = 0; k0 < 128; k0 += 16) {
            uint32_t af[2][4];
#pragma unroll
            for (int mt = 0; mt < 2; mt++) {
                int r = am + mt * 16 + g;
                af[mt][0] = *(const uint32_t*)(aS + r * KP + k0 + t * 2);
                af[mt][1] = *(const uint32_t*)(aS + (r + 8) * KP + k0 + t * 2);
                af[mt][2] = *(const uint32_t*)(aS + r * KP + k0 + 8 + t * 2);
                af[mt][3] = *(const uint32_t*)(aS + (r + 8) * KP + k0 + 8 + t * 2);
            }
#pragma unroll
            for (int nt = 0; nt < NT; nt++) {
                int n = wn * WN + nt * 8 + g;
                uint32_t b0 = *(const uint32_t*)(bS + n * KP + k0 + t * 2);
                uint32_t b1 = *(const uint32_t*)(bS + n * KP + k0 + 8 + t * 2);
                mma16816(acc[0][nt], af[0], b0, b1);
                mma16816(acc[1][nt], af[1], b0, b1);
            }
        }
    }

    // ---- epilogue: premultiply by dinv(row) = rsqrt(deg+1), fp16 stores ----
#pragma unroll
    for (int mt = 0; mt < 2; mt++) {
        int r0 = m0 + wm * 32 + mt * 16 + g;
        int r1 = r0 + 8;
        if (r0 < NN) {
            float dv = rsqrtf((float)g_cnt[r0] + 1.0f);
#pragma unroll
            for (int nt = 0; nt < NT; nt++) {
                int c = wn * WN + nt * 8 + t * 2;
                *(__half2*)&Hout[(size_t)r0 * NCOL + c] =
                    __floats2half2_rn(acc[mt][nt][0] * dv, acc[mt][nt][1] * dv);
            }
        }
        if (r1 < NN) {
            float dv = rsqrtf((float)g_cnt[r1] + 1.0f);
#pragma unroll
            for (int nt = 0; nt < NT; nt++) {
                int c = wn * WN + nt * 8 + t * 2;
                *(__half2*)&Hout[(size_t)r1 * NCOL + c] =
                    __floats2half2_rn(acc[mt][nt][2] * dv, acc[mt][nt][3] * dv);
            }
        }
    }
}

// ---------------- fused agg (premultiplied fp16 gather) + bias + BN + relu + residual (width 128) ----------------
__global__ __launch_bounds__(256) void k_agg128(
    const __half* __restrict__ linH, const float* __restrict__ resid,
    const float* __restrict__ bias, const float* __restrict__ gam,
    const float* __restrict__ bet, const float* __restrict__ mea,
    const float* __restrict__ var, float* __restrict__ out, int base, int count)
{
    __shared__ int s_c[8][32];
    int ws = threadIdx.x >> 5;
    int wl = (blockIdx.x * blockDim.x + threadIdx.x) >> 5;
    int lane = threadIdx.x & 31;
    if (wl >= count) return;
    int w = base + wl;

    int deg = g_cnt[w];
    float di = rsqrtf((float)deg + 1.0f);
    int start = w * CAP, end = start + min(deg, CAP);
    const uint2* linH2 = (const uint2*)linH;   // 4 halves per lane

    float4 acc = make_float4(0.f, 0.f, 0.f, 0.f);
    for (int e0 = start; e0 < end; e0 += 32) {
        int idx = e0 + lane;
        if (idx < end) s_c[ws][lane] = g_ecol[idx];
        __syncwarp();
        int nn = min(32, end - e0);
        int j = 0;
#pragma unroll 1
        for (; j + 4 <= nn; j += 4) {
            int c0 = s_c[ws][j + 0];
            int c1 = s_c[ws][j + 1];
            int c2 = s_c[ws][j + 2];
            int c3 = s_c[ws][j + 3];
            uint2 u0 = linH2[c0 * 32 + lane];
            uint2 u1 = linH2[c1 * 32 + lane];
            uint2 u2 = linH2[c2 * 32 + lane];
            uint2 u3 = linH2[c3 * 32 + lane];
            float2 a0 = __half22float2(*(__half2*)&u0.x), b0 = __half22float2(*(__half2*)&u0.y);
            float2 a1 = __half22float2(*(__half2*)&u1.x), b1 = __half22float2(*(__half2*)&u1.y);
            float2 a2 = __half22float2(*(__half2*)&u2.x), b2 = __half22float2(*(__half2*)&u2.y);
            float2 a3 = __half22float2(*(__half2*)&u3.x), b3 = __half22float2(*(__half2*)&u3.y);
            acc.x += a0.x + a1.x; acc.y += a0.y + a1.y;
            acc.z += b0.x + b1.x; acc.w += b0.y + b1.y;
            acc.x += a2.x + a3.x; acc.y += a2.y + a3.y;
            acc.z += b2.x + b3.x; acc.w += b2.y + b3.y;
        }
        for (; j < nn; j++) {
            int c = s_c[ws][j];
            uint2 u = linH2[c * 32 + lane];
            float2 a = __half22float2(*(__half2*)&u.x);
            float2 b = __half22float2(*(__half2*)&u.y);
            acc.x += a.x; acc.y += a.y;
            acc.z += b.x; acc.w += b.y;
        }
        __syncwarp();
    }
    // overflow edges (expected none)
    int sc = g_spillCnt;
    for (int i = 0; i < sc && i < SPILLMAX; i++) {
        int2 p = g_spill[i];
        if (p.x == w) {
            uint2 u = linH2[p.y * 32 + lane];
            float2 a = __half22float2(*(__half2*)&u.x);
            float2 b = __half22float2(*(__half2*)&u.y);
            acc.x += a.x; acc.y += a.y;
            acc.z += b.x; acc.w += b.y;
        }
    }
    // self term: + hs[w] (then whole sum * di)
    uint2 su = linH2[w * 32 + lane];
    float2 s0 = __half22float2(*(__half2*)&su.x);
    float2 s1 = __half22float2(*(__half2*)&su.y);
    acc.x += s0.x; acc.y += s0.y; acc.z += s1.x; acc.w += s1.y;

    float4 bb = ((const float4*)bias)[lane];
    float4 gg = ((const float4*)gam)[lane];
    float4 ee = ((const float4*)bet)[lane];
    float4 mm = ((const float4*)mea)[lane];
    float4 vv = ((const float4*)var)[lane];
    float sx = gg.x * rsqrtf(vv.x + 1e-5f);
    float sy = gg.y * rsqrtf(vv.y + 1e-5f);
    float sz = gg.z * rsqrtf(vv.z + 1e-5f);
    float sw = gg.w * rsqrtf(vv.w + 1e-5f);

    float4 rr = ((const float4*)resid)[w * 32 + lane];
    float4 o;
    o.x = fmaxf((fmaf(acc.x, di, bb.x) - mm.x) * sx + ee.x, 0.f) + rr.x;
    o.y = fmaxf((fmaf(acc.y, di, bb.y) - mm.y) * sy + ee.y, 0.f) + rr.y;
    o.z = fmaxf((fmaf(acc.z, di, bb.z) - mm.z) * sz + ee.z, 0.f) + rr.z;
    o.w = fmaxf((fmaf(acc.w, di, bb.w) - mm.w) * sw + ee.w, 0.f) + rr.w;
    ((float4*)out)[w * 32 + lane] = o;
}

// ---------------- final layer agg (width 64): conv + bias + BN only ----------------
__global__ __launch_bounds__(256) void k_agg64(
    const __half* __restrict__ linH,
    const float* __restrict__ bias, const float* __restrict__ gam,
    const float* __restrict__ bet, const float* __restrict__ mea,
    const float* __restrict__ var, float* __restrict__ out)
{
    __shared__ int s_c[8][32];
    int ws = threadIdx.x >> 5;
    int w = (blockIdx.x * blockDim.x + threadIdx.x) >> 5;
    int lane = threadIdx.x & 31;
    if (w >= NN) return;

    int deg = g_cnt[w];
    float di = rsqrtf((float)deg + 1.0f);
    int start = w * CAP, end = start + min(deg, CAP);
    const __half2* linH2 = (const __half2*)linH;   // 2 halves per lane

    float2 acc = make_float2(0.f, 0.f);
    for (int e0 = start; e0 < end; e0 += 32) {
        int idx = e0 + lane;
        if (idx < end) s_c[ws][lane] = g_ecol[idx];
        __syncwarp();
        int nn = min(32, end - e0);
        int j = 0;
#pragma unroll 1
        for (; j + 4 <= nn; j += 4) {
            int c0 = s_c[ws][j + 0];
            int c1 = s_c[ws][j + 1];
            int c2 = s_c[ws][j + 2];
            int c3 = s_c[ws][j + 3];
            float2 f0 = __half22float2(linH2[c0 * 32 + lane]);
            float2 f1 = __half22float2(linH2[c1 * 32 + lane]);
            float2 f2 = __half22float2(linH2[c2 * 32 + lane]);
            float2 f3 = __half22float2(linH2[c3 * 32 + lane]);
            acc.x += f0.x + f1.x; acc.y += f0.y + f1.y;
            acc.x += f2.x + f3.x; acc.y += f2.y + f3.y;
        }
        for (; j < nn; j++) {
            int c = s_c[ws][j];
            float2 f = __half22float2(linH2[c * 32 + lane]);
            acc.x += f.x; acc.y += f.y;
        }
        __syncwarp();
    }
    int sc = g_spillCnt;
    for (int i = 0; i < sc && i < SPILLMAX; i++) {
        int2 p = g_spill[i];
        if (p.x == w) {
            float2 f = __half22float2(linH2[p.y * 32 + lane]);
            acc.x += f.x; acc.y += f.y;
        }
    }
    float2 sv = __half22float2(linH2[w * 32 + lane]);
    acc.x += sv.x; acc.y += sv.y;

    float2 bb = ((const float2*)bias)[lane];
    float2 gg = ((const float2*)gam)[lane];
    float2 ee = ((const float2*)bet)[lane];
    float2 mm = ((const float2*)mea)[lane];
    float2 vv = ((const float2*)var)[lane];
    float sx = gg.x * rsqrtf(vv.x + 1e-5f);
    float sy = gg.y * rsqrtf(vv.y + 1e-5f);

    float2 o;
    o.x = (fmaf(acc.x, di, bb.x) - mm.x) * sx + ee.x;
    o.y = (fmaf(acc.y, di, bb.y) - mm.y) * sy + ee.y;
    ((float2*)out)[w * 32 + lane] = o;
}

// ---------------- launch ----------------
extern "C" void kernel_launch(void* const* d_in, const int* in_sizes, int n_in,
                              void* d_out, int out_size)
{
    const float* x    = (const float*)d_in[0];
    const void*  ei   = d_in[1];
    const float* W_in = (const float*)d_in[2];
    const float* b_in = (const float*)d_in[3];
    const float* W0 = (const float*)d_in[4];
    const float* b0 = (const float*)d_in[5];
    const float* g0 = (const float*)d_in[6];
    const float* e0 = (const float*)d_in[7];
    const float* m0 = (const float*)d_in[8];
    const float* v0 = (const float*)d_in[9];
    const float* W1 = (const float*)d_in[10];
    const float* b1 = (const float*)d_in[11];
    const float* g1 = (const float*)d_in[12];
    const float* e1 = (const float*)d_in[13];
    const float* m1 = (const float*)d_in[14];
    const float* v1 = (const float*)d_in[15];
    const float* W2 = (const float*)d_in[16];
    const float* b2 = (const float*)d_in[17];
    const float* g2 = (const float*)d_in[18];
    const float* e2 = (const float*)d_in[19];
    const float* m2 = (const float*)d_in[20];
    const float* v2 = (const float*)d_in[21];
    float* out = (float*)d_out;

    float *bufA, *bufC;
    __half *bufHA, *bufHB;
    unsigned short* wsp;
    cudaGetSymbolAddress((void**)&bufA,  g_bufA);
    cudaGetSymbolAddress((void**)&bufC,  g_bufC);
    cudaGetSymbolAddress((void**)&bufHA, g_bufHA);
    cudaGetSymbolAddress((void**)&bufHB, g_bufHB);
    cudaGetSymbolAddress((void**)&wsp,   g_Wsplit);
    unsigned short* WH0 = wsp + 0 * 128 * KP;
    unsigned short* WL0 = wsp + 1 * 128 * KP;
    unsigned short* WH1 = wsp + 2 * 128 * KP;
    unsigned short* WL1 = wsp + 3 * 128 * KP;
    unsigned short* WH2 = wsp + 4 * 128 * KP;
    unsigned short* WL2 = wsp + 5 * 128 * KP;

    const int SM128 = (2 * 128 * KP + 2 * 128 * KP) * 2;  // 139264 B
    const int SM64  = (2 * 128 * KP + 2 * 64 * KP) * 2;   // 104448 B
    cudaFuncSetAttribute(k_mma<128>, cudaFuncAttributeMaxDynamicSharedMemorySize, SM128);
    cudaFuncSetAttribute(k_mma<64>,  cudaFuncAttributeMaxDynamicSharedMemorySize, SM64);

    // lazily created side stream + fork/join events (resources only; work identical per call)
    static cudaStream_t s2 = nullptr;
    static cudaEvent_t evStart = nullptr, evPrep = nullptr;
    static cudaEvent_t evC0 = nullptr, evG0 = nullptr, evC1 = nullptr, evG1 = nullptr;
    if (!s2) {
        cudaStreamCreateWithFlags(&s2, cudaStreamNonBlocking);
        cudaEventCreateWithFlags(&evStart, cudaEventDisableTiming);
        cudaEventCreateWithFlags(&evPrep,  cudaEventDisableTiming);
        cudaEventCreateWithFlags(&evC0,    cudaEventDisableTiming);
        cudaEventCreateWithFlags(&evG0,    cudaEventDisableTiming);
        cudaEventCreateWithFlags(&evC1,    cudaEventDisableTiming);
        cudaEventCreateWithFlags(&evG1,    cudaEventDisableTiming);
    }

    const int H1 = NN - H0;                 // 49952
    const int GB0 = H0 / 128;               // 391
    const int GB1 = (H1 + 127) / 128;       // 391 (guarded)
    const int AG0 = (H0 * 32 + 255) / 256;
    const int AG1 = (H1 * 32 + 255) / 256;

    // ---- fork: side stream does weight prep + input projection ----
    cudaEventRecord(evStart, 0);
    cudaStreamWaitEvent(s2, evStart, 0);
    k_prepW<<<64, 256, 0, s2>>>(W0, 128, WH0, WL0);
    k_prepW<<<64, 256, 0, s2>>>(W1, 128, WH1, WL1);
    k_prepW<<<32, 256, 0, s2>>>(W2, 64,  WH2, WL2);
    k_inproj<<<(NN * 32 + 255) / 256, 256, 0, s2>>>(x, W_in, b_in, bufA);
    cudaEventRecord(evPrep, s2);

    // ---- main stream: single-pass bucket CSR (counts == degrees afterwards) ----
    k_zerodetect<<<(NN + 255) / 256, 256>>>((const unsigned int*)ei);
    k_fillc<<<(EE / 2 + 255) / 256, 256>>>(ei);

    // ---- layer 0 GEMM -> H_A (needs inproj + degrees) ----
    cudaStreamWaitEvent(0, evPrep, 0);
    k_mma<128><<<(NN + 127) / 128, 256, SM128>>>(bufA, WH0, WL0, bufHA, 0);

    // ---- boundary agg0(H_A) -> gemm1(H_B), chunk-pipelined (disjoint buffers) ----
    k_agg128<<<AG0, 256>>>(bufHA, bufA, b0, g0, e0, m0, v0, bufC, 0, H0);
    cudaEventRecord(evC0, 0);
    cudaStreamWaitEvent(s2, evC0, 0);
    k_mma<128><<<GB0, 256, SM128, s2>>>(bufC, WH1, WL1, bufHB, 0);     // writes H_B while agg0 reads H_A
    cudaEventRecord(evG0, s2);
    k_agg128<<<AG1, 256>>>(bufHA, bufA, b0, g0, e0, m0, v0, bufC, H0, H1);
    k_mma<128><<<GB1, 256, SM128>>>(bufC, WH1, WL1, bufHB, H0);
    cudaStreamWaitEvent(0, evG0, 0);

    // ---- boundary agg1(H_B) -> gemm64(H_A), chunk-pipelined ----
    k_agg128<<<AG0, 256>>>(bufHB, bufC, b1, g1, e1, m1, v1, bufA, 0, H0);
    cudaEventRecord(evC1, 0);
    cudaStreamWaitEvent(s2, evC1, 0);
    k_mma<64><<<GB0, 256, SM64, s2>>>(bufA, WH2, WL2, bufHA, 0);       // writes H_A while agg1 reads H_B
    cudaEventRecord(evG1, s2);
    k_agg128<<<AG1, 256>>>(bufHB, bufC, b1, g1, e1, m1, v1, bufA, H0, H1);
    k_mma<64><<<GB1, 256, SM64>>>(bufA, WH2, WL2, bufHA, H0);
    cudaStreamWaitEvent(0, evG1, 0);

    // ---- final aggregation (reads H_A) ----
    k_agg64<<<(NN * 32 + 255) / 256, 256>>>(bufHA, b2, g2, e2, m2, v2, out);
}